// round 2
// baseline (speedup 1.0000x reference)
#include <cuda_runtime.h>
#include <cuda_bf16.h>
#include <cstdint>

// ---------------------------------------------------------------------------
// EarthAttention3D: B=2, nW=840, N=144, C=192, H=6, d=32
//   qkv  = x @ w1^T + b1            (241920 x 576 x 192)
//   S    = scale*q k^T + bias + mask ; P = softmax(S) ; O = P v   per (b,w,h)
//   out  = O @ w2^T + b2            (241920 x 192 x 192)
// fp32 throughout; inner loops use packed fma.rn.f32x2 (Blackwell FFMA2).
// ---------------------------------------------------------------------------

typedef unsigned long long ull;

#define NW     840
#define NTOK   144
#define DIM    192
#define HEADS  6
#define HDIM   32
#define BATCH  2
#define MTOT   (BATCH*NW*NTOK)          // 241920
#define TABLE  3312
#define QSCALE 0.17677669529663687f     // 32^-0.5

__device__ float g_qkv[(size_t)MTOT * 576];   // 557 MB scratch
__device__ float g_att[(size_t)MTOT * DIM];   // 186 MB scratch

__device__ __forceinline__ ull pk(float x, float y) {
    ull r; asm("mov.b64 %0,{%1,%2};" : "=l"(r) : "f"(x), "f"(y)); return r;
}
__device__ __forceinline__ float2 upk(ull a) {
    float2 f; asm("mov.b64 {%0,%1},%2;" : "=f"(f.x), "=f"(f.y) : "l"(a)); return f;
}
__device__ __forceinline__ void fma2(ull& d, ull a, ull b) {
    asm("fma.rn.f32x2 %0,%1,%2,%0;" : "+l"(d) : "l"(a), "l"(b));
}

// ---------------------------------------------------------------------------
// GEMM (NT): C[m,n] = sum_k A[m,k] * W[n,k] + bias[n]
// BM=128, BN=64, BK=16, 256 threads, per-thread 8x4 via f32x2 (row pairs).
// M % 128 == 0, N % 64 == 0, K % 16 == 0 (holds for all our shapes).
// ---------------------------------------------------------------------------
__global__ __launch_bounds__(256) void gemm_nt(
    const float* __restrict__ A, const float* __restrict__ W,
    const float* __restrict__ bias, float* __restrict__ C,
    int M, int N, int K)
{
    __shared__ __align__(16) float As[16][132];
    __shared__ __align__(16) float Bs[16][68];

    const int tid = threadIdx.x;
    const int tx = tid & 15, ty = tid >> 4;
    const int bm = blockIdx.y * 128;
    const int bn = blockIdx.x * 64;

    const float* Ab = A + (size_t)bm * K;
    const float* Wb = W + (size_t)bn * K;

    ull acc[4][4];
#pragma unroll
    for (int p = 0; p < 4; p++)
#pragma unroll
        for (int j = 0; j < 4; j++) acc[p][j] = 0ULL;

    // prefetch registers
    float4 pa0, pa1, pb;
    {
        int fid0 = tid, fid1 = tid + 256;
        pa0 = *(const float4*)(Ab + (size_t)(fid0 >> 2) * K + (fid0 & 3) * 4);
        pa1 = *(const float4*)(Ab + (size_t)(fid1 >> 2) * K + (fid1 & 3) * 4);
        pb  = *(const float4*)(Wb + (size_t)(tid  >> 2) * K + (tid  & 3) * 4);
    }

    const int nkt = K / 16;
    for (int kt = 0; kt < nkt; kt++) {
        // commit prefetched tile to smem
        {
            int fid0 = tid, fid1 = tid + 256;
            int r0 = fid0 >> 2, kq0 = (fid0 & 3) * 4;
            int r1 = fid1 >> 2, kq1 = (fid1 & 3) * 4;
            As[kq0+0][r0] = pa0.x; As[kq0+1][r0] = pa0.y; As[kq0+2][r0] = pa0.z; As[kq0+3][r0] = pa0.w;
            As[kq1+0][r1] = pa1.x; As[kq1+1][r1] = pa1.y; As[kq1+2][r1] = pa1.z; As[kq1+3][r1] = pa1.w;
            int rb = tid >> 2, kqb = (tid & 3) * 4;
            Bs[kqb+0][rb] = pb.x; Bs[kqb+1][rb] = pb.y; Bs[kqb+2][rb] = pb.z; Bs[kqb+3][rb] = pb.w;
        }
        __syncthreads();

        if (kt + 1 < nkt) {
            int kbase = (kt + 1) * 16;
            int fid0 = tid, fid1 = tid + 256;
            pa0 = *(const float4*)(Ab + (size_t)(fid0 >> 2) * K + kbase + (fid0 & 3) * 4);
            pa1 = *(const float4*)(Ab + (size_t)(fid1 >> 2) * K + kbase + (fid1 & 3) * 4);
            pb  = *(const float4*)(Wb + (size_t)(tid  >> 2) * K + kbase + (tid  & 3) * 4);
        }

#pragma unroll
        for (int kk = 0; kk < 16; kk++) {
            ull ap[4];
            ap[0] = *(const ull*)&As[kk][ty * 8 + 0];
            ap[1] = *(const ull*)&As[kk][ty * 8 + 2];
            ap[2] = *(const ull*)&As[kk][ty * 8 + 4];
            ap[3] = *(const ull*)&As[kk][ty * 8 + 6];
            float4 b4 = *(const float4*)&Bs[kk][tx * 4];
            ull bd0 = pk(b4.x, b4.x), bd1 = pk(b4.y, b4.y);
            ull bd2 = pk(b4.z, b4.z), bd3 = pk(b4.w, b4.w);
#pragma unroll
            for (int p = 0; p < 4; p++) {
                fma2(acc[p][0], ap[p], bd0);
                fma2(acc[p][1], ap[p], bd1);
                fma2(acc[p][2], ap[p], bd2);
                fma2(acc[p][3], ap[p], bd3);
            }
        }
        __syncthreads();
    }

    // epilogue
    float4 bv = *(const float4*)(bias + bn + tx * 4);
#pragma unroll
    for (int p = 0; p < 4; p++) {
        float2 u0 = upk(acc[p][0]), u1 = upk(acc[p][1]);
        float2 u2 = upk(acc[p][2]), u3 = upk(acc[p][3]);
        int r0 = bm + ty * 8 + 2 * p;
        float4 o0 = make_float4(u0.x + bv.x, u1.x + bv.y, u2.x + bv.z, u3.x + bv.w);
        float4 o1 = make_float4(u0.y + bv.x, u1.y + bv.y, u2.y + bv.z, u3.y + bv.w);
        *(float4*)(C + (size_t)r0 * N + bn + tx * 4)       = o0;
        *(float4*)(C + (size_t)(r0 + 1) * N + bn + tx * 4) = o1;
    }
}

// ---------------------------------------------------------------------------
// Attention per (b, w, h). 576 threads, full-S in SMEM.
//  smem: S[144*144] | qT[32*146] | kT[32*146] | V[144*33] | bcol[3312]
// ---------------------------------------------------------------------------
#define OFS_QT 20736
#define OFS_KT (OFS_QT + 32*146)
#define OFS_V  (OFS_KT + 32*146)
#define OFS_BC (OFS_V + 144*33)
#define ATTN_SMEM ((OFS_BC + TABLE) * 4)

__global__ __launch_bounds__(576, 1) void attn_kernel(
    const float* __restrict__ qkv, const float* __restrict__ bias_table,
    const int* __restrict__ pidx, const float* __restrict__ mask,
    float* __restrict__ outp)
{
    extern __shared__ __align__(16) float sm[];
    float* S    = sm;
    float* qT   = sm + OFS_QT;
    float* kT   = sm + OFS_KT;
    float* Vv   = sm + OFS_V;
    float* bcol = sm + OFS_BC;

    const int tid = threadIdx.x;
    const int bx  = blockIdx.x;
    const int w = bx / 12;
    const int rr = bx - w * 12;
    const int b = rr / 6;
    const int h = rr - b * 6;

    const size_t base = (size_t)(b * NW + w) * NTOK * 576 + h * HDIM;
    const float* qg = qkv + base;
    const float* kg = qg + 192;
    const float* vg = qg + 384;

    // --- load q (scaled, transposed), k (transposed), v ---
    for (int idx = tid; idx < NTOK * HDIM; idx += 576) {
        int n = idx >> 5, dd = idx & 31;
        qT[dd * 146 + n] = qg[(size_t)n * 576 + dd] * QSCALE;
        kT[dd * 146 + n] = kg[(size_t)n * 576 + dd];
        Vv[n * 33 + dd]  = vg[(size_t)n * 576 + dd];
    }
    // --- stage this (w,h) bias column ---
    for (int i = tid; i < TABLE; i += 576)
        bcol[i] = bias_table[(size_t)i * (NW * HEADS) + w * HEADS + h];
    __syncthreads();

    // --- S = qT^T kT  (24x24 thread grid, 6x6 per thread, f32x2 col pairs) ---
    const int ttx = tid % 24, tty = tid / 24;
    const int i0 = tty * 6, j0 = ttx * 6;
    ull acc[6][3];
#pragma unroll
    for (int i = 0; i < 6; i++)
#pragma unroll
        for (int jp = 0; jp < 3; jp++) acc[i][jp] = 0ULL;

#pragma unroll 2
    for (int kk = 0; kk < HDIM; kk++) {
        const float* qr = qT + kk * 146 + i0;
        const float* kr = kT + kk * 146 + j0;
        ull bp0 = *(const ull*)(kr + 0);
        ull bp1 = *(const ull*)(kr + 2);
        ull bp2 = *(const ull*)(kr + 4);
#pragma unroll
        for (int i = 0; i < 6; i++) {
            float a = qr[i];
            ull ad = pk(a, a);
            fma2(acc[i][0], ad, bp0);
            fma2(acc[i][1], ad, bp1);
            fma2(acc[i][2], ad, bp2);
        }
    }

    // --- add bias + mask, store to S ---
    const float* mrow = mask + (size_t)b * NTOK * NTOK;
#pragma unroll
    for (int i = 0; i < 6; i++) {
        int n = i0 + i;
        const int*   pr = pidx + n * NTOK + j0;
        const float* mr = mrow + n * NTOK + j0;
        float* Sr = S + n * NTOK + j0;
#pragma unroll
        for (int jp = 0; jp < 3; jp++) {
            float2 pv = upk(acc[i][jp]);
            Sr[jp * 2 + 0] = pv.x + bcol[pr[jp * 2 + 0]] + mr[jp * 2 + 0];
            Sr[jp * 2 + 1] = pv.y + bcol[pr[jp * 2 + 1]] + mr[jp * 2 + 1];
        }
    }
    __syncthreads();

    // --- softmax: 18 warps x 8 rows ---
    const int wid = tid >> 5, lane = tid & 31;
    float invs[8];
#pragma unroll
    for (int i = 0; i < 8; i++) {
        int n = wid * 8 + i;
        float* Sr = S + n * NTOK;
        float mx = -1e30f;
        for (int c = lane; c < NTOK; c += 32) mx = fmaxf(mx, Sr[c]);
#pragma unroll
        for (int o = 16; o; o >>= 1) mx = fmaxf(mx, __shfl_xor_sync(0xffffffffu, mx, o));
        float sum = 0.f;
        for (int c = lane; c < NTOK; c += 32) {
            float e = __expf(Sr[c] - mx);
            Sr[c] = e;
            sum += e;
        }
#pragma unroll
        for (int o = 16; o; o >>= 1) sum += __shfl_xor_sync(0xffffffffu, sum, o);
        invs[i] = 1.0f / sum;
    }
    __syncwarp();

    // --- O = P @ v : lane = d-column, row pairs in f32x2 ---
    ull o2[4] = {0ULL, 0ULL, 0ULL, 0ULL};
#pragma unroll 2
    for (int m = 0; m < NTOK; m += 4) {
        float v0 = Vv[(m + 0) * 33 + lane];
        float v1 = Vv[(m + 1) * 33 + lane];
        float v2 = Vv[(m + 2) * 33 + lane];
        float v3 = Vv[(m + 3) * 33 + lane];
        ull vd0 = pk(v0, v0), vd1 = pk(v1, v1), vd2 = pk(v2, v2), vd3 = pk(v3, v3);
#pragma unroll
        for (int p = 0; p < 4; p++) {
            int n0 = wid * 8 + 2 * p;
            float4 s0 = *(const float4*)&S[n0 * NTOK + m];
            float4 s1 = *(const float4*)&S[(n0 + 1) * NTOK + m];
            fma2(o2[p], pk(s0.x, s1.x), vd0);
            fma2(o2[p], pk(s0.y, s1.y), vd1);
            fma2(o2[p], pk(s0.z, s1.z), vd2);
            fma2(o2[p], pk(s0.w, s1.w), vd3);
        }
    }

    float* ob = outp + (size_t)(b * NW + w) * NTOK * DIM + h * HDIM + lane;
#pragma unroll
    for (int p = 0; p < 4; p++) {
        float2 pv = upk(o2[p]);
        int n0 = wid * 8 + 2 * p;
        ob[(size_t)n0 * DIM]       = pv.x * invs[2 * p];
        ob[(size_t)(n0 + 1) * DIM] = pv.y * invs[2 * p + 1];
    }
}

// ---------------------------------------------------------------------------
extern "C" void kernel_launch(void* const* d_in, const int* in_sizes, int n_in,
                              void* d_out, int out_size)
{
    const float* x    = (const float*)d_in[0];
    const float* mask = (const float*)d_in[1];
    const float* w1   = (const float*)d_in[2];
    const float* b1   = (const float*)d_in[3];
    const float* w2   = (const float*)d_in[4];
    const float* b2   = (const float*)d_in[5];
    const float* bt   = (const float*)d_in[6];
    const int*   pidx = (const int*)d_in[7];
    float* out = (float*)d_out;

    void *qkv_p, *att_p;
    cudaGetSymbolAddress(&qkv_p, g_qkv);
    cudaGetSymbolAddress(&att_p, g_att);
    float* qkv = (float*)qkv_p;
    float* att = (float*)att_p;

    cudaFuncSetAttribute(attn_kernel, cudaFuncAttributeMaxDynamicSharedMemorySize, ATTN_SMEM);

    // QKV projection: 241920 x 576 x 192
    gemm_nt<<<dim3(576 / 64, MTOT / 128), 256>>>(x, w1, b1, qkv, MTOT, 576, DIM);
    // fused attention per (b, w, h); CTAs w-major for L2 bias reuse
    attn_kernel<<<NW * BATCH * HEADS, 576, ATTN_SMEM>>>(qkv, bt, pidx, mask, att);
    // output projection: 241920 x 192 x 192
    gemm_nt<<<dim3(DIM / 64, MTOT / 128), 256>>>(att, w2, b2, out, MTOT, DIM, DIM);
}